// round 14
// baseline (speedup 1.0000x reference)
#include <cuda_runtime.h>
#include <cuda_fp16.h>
#include <math.h>
#include <stdint.h>

// Problem constants
#define Nn 512
#define Bb 64
#define Ff 128
#define Oo 128
#define Ee 3
#define Mrows (Nn*Bb)     // 32768
#define Jcols 512         // 3*O + O(highway)

// Scratch (static device globals)
__device__ float g_t[(size_t)Mrows*Oo];          // sigmoid gate [m, o]
__device__ float g_h[(size_t)Mrows*Oo];          // layer-1 output fp32 (highway X)
__device__ float g_bcat[2*Jcols];
__device__ __half g_WcatH[2*Ff*Jcols];           // weights fp16 (both layers)
__device__ __half g_xH[(size_t)Mrows*Ff];        // layer-1 X fp16
__device__ __half g_hH[(size_t)Mrows*Ff];        // layer-2 X fp16
__device__ __half g_supH[(size_t)Ee*Bb*Nn*Oo];   // support fp16 [e,b,n,o]
__device__ __half g_adjH[(size_t)Ee*Bb*Nn*Nn];   // adj fp16 (emitted by L1 gemm2)

// ---- fp16 convert ----
__device__ __forceinline__ uint32_t cvt16(float x, float y) {
    __half2 h = __floats2half2_rn(x, y);
    return *reinterpret_cast<uint32_t*>(&h);
}

__device__ __forceinline__ uint32_t smem_u32(const void* p) {
    uint32_t a;
    asm("{ .reg .u64 t; cvta.to.shared.u64 t, %1; cvt.u32.u64 %0, t; }" : "=r"(a) : "l"(p));
    return a;
}

// ---- cp.async ----
__device__ __forceinline__ void cpa16(uint32_t saddr, const void* g) {
    asm volatile("cp.async.cg.shared.global [%0], [%1], 16;" :: "r"(saddr), "l"(g));
}
__device__ __forceinline__ void cpa_commit() {
    asm volatile("cp.async.commit_group;" ::: "memory");
}
__device__ __forceinline__ void cpa_wait0() {
    asm volatile("cp.async.wait_group 0;" ::: "memory");
}
__device__ __forceinline__ void cpa_wait1() {
    asm volatile("cp.async.wait_group 1;" ::: "memory");
}

// ---- warp-level MMA primitives (fp16 in, fp32 accum) ----
__device__ __forceinline__ void ldsm4(uint32_t r[4], uint32_t addr) {
    asm volatile("ldmatrix.sync.aligned.m8n8.x4.shared.b16 {%0,%1,%2,%3}, [%4];"
                 : "=r"(r[0]), "=r"(r[1]), "=r"(r[2]), "=r"(r[3]) : "r"(addr));
}
__device__ __forceinline__ void ldsm4t(uint32_t r[4], uint32_t addr) {
    asm volatile("ldmatrix.sync.aligned.m8n8.x4.trans.shared.b16 {%0,%1,%2,%3}, [%4];"
                 : "=r"(r[0]), "=r"(r[1]), "=r"(r[2]), "=r"(r[3]) : "r"(addr));
}
__device__ __forceinline__ void mma16816(float c[4], const uint32_t a[4], const uint32_t b[2]) {
    asm volatile(
        "mma.sync.aligned.m16n8k16.row.col.f32.f16.f16.f32 "
        "{%0,%1,%2,%3}, {%4,%5,%6,%7}, {%8,%9}, {%0,%1,%2,%3};"
        : "+f"(c[0]), "+f"(c[1]), "+f"(c[2]), "+f"(c[3])
        : "r"(a[0]), "r"(a[1]), "r"(a[2]), "r"(a[3]), "r"(b[0]), "r"(b[1]));
}

// ---- shared tile geometry ----
// gemm2 (BK=32 chunks):
#define ASTR 40       // A smem row stride (half elems), 80 B
#define BSTR 136      // B smem row stride (half elems), 272 B
#define A_PLANE 10240 // 128*40*2
#define B_PLANE 8704  // 32*136*2
#define BH_OFF A_PLANE
#define BUFSTRIDE (A_PLANE + B_PLANE)   // 18944
#define SMEM_3B (3*BUFSTRIDE)           // 56832 (gemm2 L2, 3-stage)
#define SMEM_2B (2*BUFSTRIDE)           // 37888 (gemm2 L1, 2-stage)
// gemm1 (A resident, 2 B buffers, full K=128):
#define ASTR1 136
#define TILE_BYTES (128*ASTR1*2)        // 34816 (A or one B buffer)
#define SMEM_G1 (3*TILE_BYTES)          // 104448

// 1-pass compute on a BK=32 staged buffer. 2x4 warp grid, 64x32 warp tiles.
__device__ __forceinline__ void mma_compute1(uint32_t sb, int lane, int wm, int wn,
                                             float acc[4][4][4]) {
    #pragma unroll
    for (int ks = 0; ks < 2; ++ks) {
        int k0 = ks * 16;
        uint32_t abase = sb + ((wm * 64 + (lane & 15)) * ASTR + k0 + ((lane >> 4) << 3)) * 2;
        uint32_t bbase = sb + ((k0 + (lane & 15)) * BSTR + wn * 32 + ((lane >> 4) << 3)) * 2;

        uint32_t ah[4][4], bhf[4][2];
        #pragma unroll
        for (int mi = 0; mi < 4; ++mi)
            ldsm4(ah[mi], abase + mi * 16 * ASTR * 2);
        #pragma unroll
        for (int g = 0; g < 2; ++g) {
            uint32_t r[4];
            ldsm4t(r, bbase + BH_OFF + g * 32);
            bhf[g*2][0] = r[0]; bhf[g*2][1] = r[1];
            bhf[g*2+1][0] = r[2]; bhf[g*2+1][1] = r[3];
        }
        #pragma unroll
        for (int mi = 0; mi < 4; ++mi)
            #pragma unroll
            for (int ni = 0; ni < 4; ++ni)
                mma16816(acc[mi][ni], ah[mi], bhf[ni]);
    }
}

// full-K compute for gemm1: A resident at abuf (ASTR1), B at bbuf (BSTR rows)
__device__ __forceinline__ void mma_compute_full(uint32_t abuf, uint32_t bbuf,
                                                 int lane, int wm, int wn,
                                                 float acc[4][4][4]) {
    #pragma unroll
    for (int ks = 0; ks < 8; ++ks) {
        int k0 = ks * 16;
        uint32_t abase = abuf + ((wm * 64 + (lane & 15)) * ASTR1 + k0 + ((lane >> 4) << 3)) * 2;
        uint32_t bbase = bbuf + ((k0 + (lane & 15)) * BSTR + wn * 32 + ((lane >> 4) << 3)) * 2;

        uint32_t ah[4][4], bhf[4][2];
        #pragma unroll
        for (int mi = 0; mi < 4; ++mi)
            ldsm4(ah[mi], abase + mi * 16 * ASTR1 * 2);
        #pragma unroll
        for (int g = 0; g < 2; ++g) {
            uint32_t r[4];
            ldsm4t(r, bbase + g * 32);
            bhf[g*2][0] = r[0]; bhf[g*2][1] = r[1];
            bhf[g*2+1][0] = r[2]; bhf[g*2+1][1] = r[3];
        }
        #pragma unroll
        for (int mi = 0; mi < 4; ++mi)
            #pragma unroll
            for (int ni = 0; ni < 4; ++ni)
                mma16816(acc[mi][ni], ah[mi], bhf[ni]);
    }
}

// ---------------------------------------------------------------------------
// prep_weights: W/Wh -> fp16 plane [f][j] at slot widx, biases fp32
// ---------------------------------------------------------------------------
__global__ void prep_weights(const float* __restrict__ W, const float* __restrict__ b,
                             const float* __restrict__ Wh, const float* __restrict__ bh,
                             int widx) {
    int idx = blockIdx.x * blockDim.x + threadIdx.x;
    if (idx < Ff * Jcols / 2) {
        int f = idx / (Jcols / 2), jp = idx % (Jcols / 2);
        int j = jp * 2;
        float v0, v1;
        if (j < 3 * Oo) {
            int e = j >> 7, o = j & 127;
            v0 = W[((size_t)e * Ff + f) * Oo + o];
            v1 = W[((size_t)e * Ff + f) * Oo + o + 1];
        } else {
            v0 = Wh[(size_t)f * Oo + (j - 3 * Oo)];
            v1 = Wh[(size_t)f * Oo + (j - 3 * Oo) + 1];
        }
        *(uint32_t*)&g_WcatH[widx * (Ff * Jcols) + f * Jcols + j] = cvt16(v0, v1);
    }
    if (idx < Jcols) {
        int j = idx;
        g_bcat[widx * Jcols + j] = (j < 3 * Oo) ? b[(j >> 7) * Oo + (j & 127)]
                                                : bh[j - 3 * Oo];
    }
}

// ---------------------------------------------------------------------------
// x_split: fp32 [m,f] -> fp16 plane (layer-1 X)
// ---------------------------------------------------------------------------
__global__ void x_split(const float* __restrict__ x) {
    int i = blockIdx.x * blockDim.x + threadIdx.x;   // over float4 slots
    float4 v = ((const float4*)x)[i];
    ((uint2*)g_xH)[i] = make_uint2(cvt16(v.x, v.y), cvt16(v.z, v.w));
}

// ---------------------------------------------------------------------------
// GEMM1 (fp16, A resident, jb-loop inside): C = X @ Wcat + bias, all 512 cols
// grid = Mrows/128 = 256 CTAs (one wave at 2 CTA/SM).
// Refill of B buffer (jb&1) happens only AFTER the post-epilogue barrier —
// this is the race fix vs R12.
// ---------------------------------------------------------------------------
__global__ __launch_bounds__(256, 2) void gemm1_mma(int x_from_h, int widx) {
    extern __shared__ char smem[];
    const __half* __restrict__ XH = x_from_h ? g_hH : g_xH;
    const __half* __restrict__ WH = g_WcatH + (size_t)widx * Ff * Jcols;
    uint32_t sbase = smem_u32(smem);

    int tid = threadIdx.x, lane = tid & 31, wid = tid >> 5;
    int wm = wid & 1, wn = wid >> 1;
    int m0 = blockIdx.x * 128;

    auto issueB = [&](int jb) {
        uint32_t bb = sbase + TILE_BYTES + (jb & 1) * TILE_BYTES;
        #pragma unroll
        for (int q = 0; q < 8; ++q) {
            int i = q * 256 + tid;
            int row = i >> 4, c16 = i & 15;
            cpa16(bb + row * (BSTR * 2) + c16 * 16,
                  WH + (size_t)row * Jcols + jb * 128 + c16 * 8);
        }
        cpa_commit();
    };

    // group0: A tile + B0
    #pragma unroll
    for (int q = 0; q < 8; ++q) {
        int i = q * 256 + tid;
        int row = i >> 4, c16 = i & 15;
        cpa16(sbase + row * (ASTR1 * 2) + c16 * 16,
              XH + (size_t)(m0 + row) * Ff + c16 * 8);
    }
    issueB(0);
    issueB(1);   // group1

    #pragma unroll
    for (int jb = 0; jb < 4; ++jb) {
        if (jb < 3) cpa_wait1(); else cpa_wait0();
        __syncthreads();

        float acc[4][4][4];
        #pragma unroll
        for (int mi = 0; mi < 4; ++mi)
            #pragma unroll
            for (int ni = 0; ni < 4; ++ni)
                #pragma unroll
                for (int r = 0; r < 4; ++r) acc[mi][ni][r] = 0.f;

        mma_compute_full(sbase, sbase + TILE_BYTES + (jb & 1) * TILE_BYTES,
                         lane, wm, wn, acc);

        // per-jb epilogue
        #pragma unroll
        for (int mi = 0; mi < 4; ++mi) {
            #pragma unroll
            for (int ni = 0; ni < 4; ++ni) {
                int col = wn * 32 + ni * 8 + (lane & 3) * 2;
                float bb0 = g_bcat[widx * Jcols + jb * 128 + col];
                float bb1 = g_bcat[widx * Jcols + jb * 128 + col + 1];
                #pragma unroll
                for (int h = 0; h < 2; ++h) {
                    int m = m0 + wm * 64 + mi * 16 + (lane >> 2) + h * 8;
                    float d0 = acc[mi][ni][h * 2 + 0] + bb0;
                    float d1 = acc[mi][ni][h * 2 + 1] + bb1;
                    if (jb < 3) {
                        int n = m >> 6, bidx = m & 63;
                        size_t off = (((size_t)jb * Bb + bidx) * Nn + n) * Oo + col;
                        *(uint32_t*)&g_supH[off] = cvt16(d0, d1);
                    } else {
                        float2 r;
                        r.x = 1.f / (1.f + expf(-d0));
                        r.y = 1.f / (1.f + expf(-d1));
                        *(float2*)&g_t[(size_t)m * Oo + col] = r;
                    }
                }
            }
        }

        // refill this jb's buffer for jb+2 only after all warps finished reading it
        if (jb + 2 < 4) {
            __syncthreads();
            issueB(jb + 2);
        }
    }
}

// ---------------------------------------------------------------------------
// GEMM2 layer 1 (fp32 adj, register cvt, EMITS g_adjH): -> g_h (+g_hH)
// grid (4, 64). NCH=48, double-buffered. Wide (16B) A staging.
// ---------------------------------------------------------------------------
#define NCH2 48

__global__ __launch_bounds__(256, 2) void gemm2_mma(const float* __restrict__ adj,
                                                    const float* __restrict__ Xin) {
    extern __shared__ char smem[];
    uint32_t sbase = smem_u32(smem);

    int tid = threadIdx.x, lane = tid & 31, wid = tid >> 5;
    int wm = wid & 1, wn = wid >> 1;
    int m0 = blockIdx.x * 128, b = blockIdx.y;

    float acc[4][4][4];
    #pragma unroll
    for (int mi = 0; mi < 4; ++mi)
        #pragma unroll
        for (int ni = 0; ni < 4; ++ni)
            #pragma unroll
            for (int r = 0; r < 4; ++r) acc[mi][ni][r] = 0.f;

    int arow[2], ac8[2];
    #pragma unroll
    for (int q = 0; q < 2; ++q) { int s = q * 256 + tid; arow[q] = s >> 2; ac8[q] = s & 3; }
    float4 av[2][2];

    auto issueB = [&](int c) {
        uint32_t sb = sbase + (c & 1) * BUFSTRIDE;
        int e = c >> 4, n0 = (c & 15) * 32;
        size_t gb = (((size_t)e * Bb + b) * Nn + n0) * Oo;
        #pragma unroll
        for (int q = 0; q < 2; ++q) {
            int i = q * 256 + tid;
            int row = i >> 4, c8 = i & 15;
            cpa16(sb + BH_OFF + row * (BSTR * 2) + c8 * 16,
                  g_supH + gb + (size_t)row * Oo + c8 * 8);
        }
        cpa_commit();
    };
    auto loadA = [&](int c) {
        int e = c >> 4, n0 = (c & 15) * 32;
        const float* ab = adj + (((size_t)e * Bb + b) * Nn + m0) * Nn + n0;
        #pragma unroll
        for (int q = 0; q < 2; ++q) {
            const float* p = ab + (size_t)arow[q] * Nn + ac8[q] * 8;
            av[q][0] = *(const float4*)p;
            av[q][1] = *(const float4*)(p + 4);
        }
    };
    auto storeA = [&](int c) {
        uint32_t off = (c & 1) * BUFSTRIDE;
        int e = c >> 4, n0 = (c & 15) * 32;
        size_t ah_base = (((size_t)e * Bb + b) * Nn + m0) * Nn + n0;
        #pragma unroll
        for (int q = 0; q < 2; ++q) {
            uint4 hv;
            hv.x = cvt16(av[q][0].x, av[q][0].y);
            hv.y = cvt16(av[q][0].z, av[q][0].w);
            hv.z = cvt16(av[q][1].x, av[q][1].y);
            hv.w = cvt16(av[q][1].z, av[q][1].w);
            *(uint4*)(smem + off + arow[q] * (ASTR * 2) + ac8[q] * 16) = hv;
            *(uint4*)&g_adjH[ah_base + (size_t)arow[q] * Nn + ac8[q] * 8] = hv;
        }
    };

    issueB(0);
    loadA(0);
    storeA(0);
    for (int c = 0; c < NCH2; ++c) {
        cpa_wait0();
        __syncthreads();
        if (c + 1 < NCH2) { issueB(c + 1); loadA(c + 1); }
        mma_compute1(sbase + (c & 1) * BUFSTRIDE, lane, wm, wn, acc);
        if (c + 1 < NCH2) storeA(c + 1);
    }

    // epilogue: relu + highway gate -> g_h fp32 + g_hH fp16
    #pragma unroll
    for (int mi = 0; mi < 4; ++mi) {
        #pragma unroll
        for (int ni = 0; ni < 4; ++ni) {
            int col = wn * 32 + ni * 8 + (lane & 3) * 2;
            #pragma unroll
            for (int h = 0; h < 2; ++h) {
                int row = m0 + wm * 64 + mi * 16 + (lane >> 2) + h * 8;
                float d0 = acc[mi][ni][h * 2 + 0];
                float d1 = acc[mi][ni][h * 2 + 1];
                size_t base = ((size_t)row * Bb + b) * Oo + col;
                float2 tv = *(const float2*)&g_t[base];
                float2 xv = *(const float2*)&Xin[base];
                float2 r;
                r.x = fmaxf(d0, 0.f) * tv.x + xv.x * (1.f - tv.x);
                r.y = fmaxf(d1, 0.f) * tv.y + xv.y * (1.f - tv.y);
                *(float2*)&g_h[base] = r;
                *(uint32_t*)&g_hH[base] = cvt16(r.x, r.y);
            }
        }
    }
}

// ---------------------------------------------------------------------------
// GEMM2 layer 2 (pure fp16, 3-stage cp.async): -> d_out
// grid (4, 64). A from g_adjH, B from g_supH.
// ---------------------------------------------------------------------------
__global__ __launch_bounds__(256, 2) void gemm2_f16(float* __restrict__ Out) {
    extern __shared__ char smem[];
    uint32_t sbase = smem_u32(smem);

    int tid = threadIdx.x, lane = tid & 31, wid = tid >> 5;
    int wm = wid & 1, wn = wid >> 1;
    int m0 = blockIdx.x * 128, b = blockIdx.y;

    float acc[4][4][4];
    #pragma unroll
    for (int mi = 0; mi < 4; ++mi)
        #pragma unroll
        for (int ni = 0; ni < 4; ++ni)
            #pragma unroll
            for (int r = 0; r < 4; ++r) acc[mi][ni][r] = 0.f;

    auto issue = [&](int c) {
        uint32_t sb = sbase + (c % 3) * BUFSTRIDE;
        int e = c >> 4, n0 = (c & 15) * 32;
        size_t ab = (((size_t)e * Bb + b) * Nn + m0) * Nn + n0;
        #pragma unroll
        for (int q = 0; q < 2; ++q) {           // A: 128 rows x 32 halfs
            int i = q * 256 + tid;
            int row = i >> 2, c4 = i & 3;
            cpa16(sb + row * (ASTR * 2) + c4 * 16,
                  g_adjH + ab + (size_t)row * Nn + c4 * 8);
        }
        size_t gb = (((size_t)e * Bb + b) * Nn + n0) * Oo;
        #pragma unroll
        for (int q = 0; q < 2; ++q) {           // B: 32 rows x 128 cols
            int i = q * 256 + tid;
            int row = i >> 4, c8 = i & 15;
            cpa16(sb + BH_OFF + row * (BSTR * 2) + c8 * 16,
                  g_supH + gb + (size_t)row * Oo + c8 * 8);
        }
        cpa_commit();
    };

    issue(0);
    issue(1);
    for (int c = 0; c < NCH2; ++c) {
        if (c + 1 < NCH2) cpa_wait1(); else cpa_wait0();
        __syncthreads();
        if (c + 2 < NCH2) issue(c + 2);
        mma_compute1(sbase + (c % 3) * BUFSTRIDE, lane, wm, wn, acc);
    }

    // epilogue: relu + highway gate -> d_out
    #pragma unroll
    for (int mi = 0; mi < 4; ++mi) {
        #pragma unroll
        for (int ni = 0; ni < 4; ++ni) {
            int col = wn * 32 + ni * 8 + (lane & 3) * 2;
            #pragma unroll
            for (int h = 0; h < 2; ++h) {
                int row = m0 + wm * 64 + mi * 16 + (lane >> 2) + h * 8;
                float d0 = acc[mi][ni][h * 2 + 0];
                float d1 = acc[mi][ni][h * 2 + 1];
                size_t base = ((size_t)row * Bb + b) * Oo + col;
                float2 tv = *(const float2*)&g_t[base];
                float2 xv = *(const float2*)&g_h[base];
                float2 r;
                r.x = fmaxf(d0, 0.f) * tv.x + xv.x * (1.f - tv.x);
                r.y = fmaxf(d1, 0.f) * tv.y + xv.y * (1.f - tv.y);
                *(float2*)&Out[base] = r;
            }
        }
    }
}

extern "C" void kernel_launch(void* const* d_in, const int* in_sizes, int n_in,
                              void* d_out, int out_size) {
    const float* x   = (const float*)d_in[0];
    const float* adj = (const float*)d_in[1];
    const float* W1  = (const float*)d_in[2];
    const float* b1  = (const float*)d_in[3];
    const float* Wh1 = (const float*)d_in[4];
    const float* bh1 = (const float*)d_in[5];
    const float* W2  = (const float*)d_in[6];
    const float* b2  = (const float*)d_in[7];
    const float* Wh2 = (const float*)d_in[8];
    const float* bh2 = (const float*)d_in[9];
    float* out = (float*)d_out;

    static int attr_done = 0;
    if (!attr_done) {
        cudaFuncSetAttribute(gemm1_mma, cudaFuncAttributeMaxDynamicSharedMemorySize, SMEM_G1);
        cudaFuncSetAttribute(gemm2_mma, cudaFuncAttributeMaxDynamicSharedMemorySize, SMEM_2B);
        cudaFuncSetAttribute(gemm2_f16, cudaFuncAttributeMaxDynamicSharedMemorySize, SMEM_3B);
        attr_done = 1;
    }

    dim3 g2(Nn / 128, Bb);     // (4, 64)

    // Both weight preps up front
    prep_weights<<<Ff * Jcols / 2 / 256, 256>>>(W1, b1, Wh1, bh1, 0);
    prep_weights<<<Ff * Jcols / 2 / 256, 256>>>(W2, b2, Wh2, bh2, 1);
    x_split<<<Mrows * Ff / 4 / 256, 256>>>(x);

    // Layer 1
    gemm1_mma<<<Mrows / 128, 256, SMEM_G1>>>(0, 0);
    gemm2_mma<<<g2, 256, SMEM_2B>>>(adj, x);        // -> g_h, g_hH, g_adjH
    // Layer 2
    gemm1_mma<<<Mrows / 128, 256, SMEM_G1>>>(1, 1);
    gemm2_f16<<<g2, 256, SMEM_3B>>>(out);           // -> d_out
}

// round 15
// speedup vs baseline: 1.0463x; 1.0463x over previous
#include <cuda_runtime.h>
#include <cuda_fp16.h>
#include <math.h>
#include <stdint.h>

// Problem constants
#define Nn 512
#define Bb 64
#define Ff 128
#define Oo 128
#define Ee 3
#define Mrows (Nn*Bb)     // 32768
#define Jcols 512         // 3*O + O(highway)

// Scratch (static device globals)
__device__ float g_t[(size_t)Mrows*Oo];          // sigmoid gate [m, o]
__device__ float g_h[(size_t)Mrows*Oo];          // layer-1 output fp32 (highway X)
__device__ float g_bcat[2*Jcols];
__device__ __half g_WcatH[2*Ff*Jcols];           // weights fp16 (both layers)
__device__ __half g_xH[(size_t)Mrows*Ff];        // layer-1 X fp16
__device__ __half g_hH[(size_t)Mrows*Ff];        // layer-2 X fp16
__device__ __half g_supH[(size_t)Ee*Bb*Nn*Oo];   // support fp16 [e,b,n,o]
__device__ __half g_adjH[(size_t)Ee*Bb*Nn*Nn];   // adj fp16 (emitted by L1 gemm2)

// ---- fp16 convert ----
__device__ __forceinline__ uint32_t cvt16(float x, float y) {
    __half2 h = __floats2half2_rn(x, y);
    return *reinterpret_cast<uint32_t*>(&h);
}

__device__ __forceinline__ uint32_t smem_u32(const void* p) {
    uint32_t a;
    asm("{ .reg .u64 t; cvta.to.shared.u64 t, %1; cvt.u32.u64 %0, t; }" : "=r"(a) : "l"(p));
    return a;
}

// ---- cp.async ----
__device__ __forceinline__ void cpa16(uint32_t saddr, const void* g) {
    asm volatile("cp.async.cg.shared.global [%0], [%1], 16;" :: "r"(saddr), "l"(g));
}
__device__ __forceinline__ void cpa_commit() {
    asm volatile("cp.async.commit_group;" ::: "memory");
}
__device__ __forceinline__ void cpa_wait0() {
    asm volatile("cp.async.wait_group 0;" ::: "memory");
}
__device__ __forceinline__ void cpa_wait1() {
    asm volatile("cp.async.wait_group 1;" ::: "memory");
}

// ---- warp-level MMA primitives (fp16 in, fp32 accum) ----
__device__ __forceinline__ void ldsm4(uint32_t r[4], uint32_t addr) {
    asm volatile("ldmatrix.sync.aligned.m8n8.x4.shared.b16 {%0,%1,%2,%3}, [%4];"
                 : "=r"(r[0]), "=r"(r[1]), "=r"(r[2]), "=r"(r[3]) : "r"(addr));
}
__device__ __forceinline__ void ldsm4t(uint32_t r[4], uint32_t addr) {
    asm volatile("ldmatrix.sync.aligned.m8n8.x4.trans.shared.b16 {%0,%1,%2,%3}, [%4];"
                 : "=r"(r[0]), "=r"(r[1]), "=r"(r[2]), "=r"(r[3]) : "r"(addr));
}
__device__ __forceinline__ void mma16816(float c[4], const uint32_t a[4], const uint32_t b[2]) {
    asm volatile(
        "mma.sync.aligned.m16n8k16.row.col.f32.f16.f16.f32 "
        "{%0,%1,%2,%3}, {%4,%5,%6,%7}, {%8,%9}, {%0,%1,%2,%3};"
        : "+f"(c[0]), "+f"(c[1]), "+f"(c[2]), "+f"(c[3])
        : "r"(a[0]), "r"(a[1]), "r"(a[2]), "r"(a[3]), "r"(b[0]), "r"(b[1]));
}

// ---- shared tile geometry ----
// gemm2 (BK=32 chunks):
#define ASTR 40       // A smem row stride (half elems), 80 B
#define BSTR 136      // B smem row stride (half elems), 272 B
#define A_PLANE 10240 // 128*40*2
#define B_PLANE 8704  // 32*136*2
#define BH_OFF A_PLANE
#define BUFSTRIDE (A_PLANE + B_PLANE)   // 18944
#define SMEM_3B (3*BUFSTRIDE)           // 56832 (gemm2 L2, 3-stage)
#define SMEM_2B (2*BUFSTRIDE)           // 37888 (gemm2 L1, 2-stage)
// gemm1 (A resident, 2 B buffers, full K=128):
#define ASTR1 136
#define TILE_BYTES (128*ASTR1*2)        // 34816 (A or one B buffer; also epi staging)
#define SMEM_G1 (3*TILE_BYTES)          // 104448

// 1-pass compute on a BK=32 staged buffer. 2x4 warp grid, 64x32 warp tiles.
__device__ __forceinline__ void mma_compute1(uint32_t sb, int lane, int wm, int wn,
                                             float acc[4][4][4]) {
    #pragma unroll
    for (int ks = 0; ks < 2; ++ks) {
        int k0 = ks * 16;
        uint32_t abase = sb + ((wm * 64 + (lane & 15)) * ASTR + k0 + ((lane >> 4) << 3)) * 2;
        uint32_t bbase = sb + ((k0 + (lane & 15)) * BSTR + wn * 32 + ((lane >> 4) << 3)) * 2;

        uint32_t ah[4][4], bhf[4][2];
        #pragma unroll
        for (int mi = 0; mi < 4; ++mi)
            ldsm4(ah[mi], abase + mi * 16 * ASTR * 2);
        #pragma unroll
        for (int g = 0; g < 2; ++g) {
            uint32_t r[4];
            ldsm4t(r, bbase + BH_OFF + g * 32);
            bhf[g*2][0] = r[0]; bhf[g*2][1] = r[1];
            bhf[g*2+1][0] = r[2]; bhf[g*2+1][1] = r[3];
        }
        #pragma unroll
        for (int mi = 0; mi < 4; ++mi)
            #pragma unroll
            for (int ni = 0; ni < 4; ++ni)
                mma16816(acc[mi][ni], ah[mi], bhf[ni]);
    }
}

// full-K compute for gemm1: A resident at abuf (ASTR1), B at bbuf (BSTR rows)
__device__ __forceinline__ void mma_compute_full(uint32_t abuf, uint32_t bbuf,
                                                 int lane, int wm, int wn,
                                                 float acc[4][4][4]) {
    #pragma unroll
    for (int ks = 0; ks < 8; ++ks) {
        int k0 = ks * 16;
        uint32_t abase = abuf + ((wm * 64 + (lane & 15)) * ASTR1 + k0 + ((lane >> 4) << 3)) * 2;
        uint32_t bbase = bbuf + ((k0 + (lane & 15)) * BSTR + wn * 32 + ((lane >> 4) << 3)) * 2;

        uint32_t ah[4][4], bhf[4][2];
        #pragma unroll
        for (int mi = 0; mi < 4; ++mi)
            ldsm4(ah[mi], abase + mi * 16 * ASTR1 * 2);
        #pragma unroll
        for (int g = 0; g < 2; ++g) {
            uint32_t r[4];
            ldsm4t(r, bbase + g * 32);
            bhf[g*2][0] = r[0]; bhf[g*2][1] = r[1];
            bhf[g*2+1][0] = r[2]; bhf[g*2+1][1] = r[3];
        }
        #pragma unroll
        for (int mi = 0; mi < 4; ++mi)
            #pragma unroll
            for (int ni = 0; ni < 4; ++ni)
                mma16816(acc[mi][ni], ah[mi], bhf[ni]);
    }
}

// ---------------------------------------------------------------------------
// prep_weights: W/Wh -> fp16 plane [f][j] at slot widx, biases fp32
// ---------------------------------------------------------------------------
__global__ void prep_weights(const float* __restrict__ W, const float* __restrict__ b,
                             const float* __restrict__ Wh, const float* __restrict__ bh,
                             int widx) {
    int idx = blockIdx.x * blockDim.x + threadIdx.x;
    if (idx < Ff * Jcols / 2) {
        int f = idx / (Jcols / 2), jp = idx % (Jcols / 2);
        int j = jp * 2;
        float v0, v1;
        if (j < 3 * Oo) {
            int e = j >> 7, o = j & 127;
            v0 = W[((size_t)e * Ff + f) * Oo + o];
            v1 = W[((size_t)e * Ff + f) * Oo + o + 1];
        } else {
            v0 = Wh[(size_t)f * Oo + (j - 3 * Oo)];
            v1 = Wh[(size_t)f * Oo + (j - 3 * Oo) + 1];
        }
        *(uint32_t*)&g_WcatH[widx * (Ff * Jcols) + f * Jcols + j] = cvt16(v0, v1);
    }
    if (idx < Jcols) {
        int j = idx;
        g_bcat[widx * Jcols + j] = (j < 3 * Oo) ? b[(j >> 7) * Oo + (j & 127)]
                                                : bh[j - 3 * Oo];
    }
}

// ---------------------------------------------------------------------------
// x_split: fp32 [m,f] -> fp16 plane (layer-1 X)
// ---------------------------------------------------------------------------
__global__ void x_split(const float* __restrict__ x) {
    int i = blockIdx.x * blockDim.x + threadIdx.x;   // over float4 slots
    float4 v = ((const float4*)x)[i];
    ((uint2*)g_xH)[i] = make_uint2(cvt16(v.x, v.y), cvt16(v.z, v.w));
}

// ---------------------------------------------------------------------------
// GEMM1 (fp16, A resident, jb-loop inside): C = X @ Wcat + bias, all 512 cols
// grid = Mrows/128 = 256 CTAs. Support epilogue (jb<3) is smem-staged so the
// [e,b,n,o] stores are fully coalesced (fixes the 8-sector scatter).
// ---------------------------------------------------------------------------
__global__ __launch_bounds__(256, 2) void gemm1_mma(int x_from_h, int widx) {
    extern __shared__ char smem[];
    const __half* __restrict__ XH = x_from_h ? g_hH : g_xH;
    const __half* __restrict__ WH = g_WcatH + (size_t)widx * Ff * Jcols;
    uint32_t sbase = smem_u32(smem);

    int tid = threadIdx.x, lane = tid & 31, wid = tid >> 5;
    int wm = wid & 1, wn = wid >> 1;
    int m0 = blockIdx.x * 128;

    auto issueB = [&](int jb) {
        uint32_t bb = sbase + TILE_BYTES + (jb & 1) * TILE_BYTES;
        #pragma unroll
        for (int q = 0; q < 8; ++q) {
            int i = q * 256 + tid;
            int row = i >> 4, c16 = i & 15;
            cpa16(bb + row * (BSTR * 2) + c16 * 16,
                  WH + (size_t)row * Jcols + jb * 128 + c16 * 8);
        }
        cpa_commit();
    };

    // group0: A tile + B0
    #pragma unroll
    for (int q = 0; q < 8; ++q) {
        int i = q * 256 + tid;
        int row = i >> 4, c16 = i & 15;
        cpa16(sbase + row * (ASTR1 * 2) + c16 * 16,
              XH + (size_t)(m0 + row) * Ff + c16 * 8);
    }
    issueB(0);
    issueB(1);   // group1

    #pragma unroll
    for (int jb = 0; jb < 4; ++jb) {
        if (jb < 3) cpa_wait1(); else cpa_wait0();
        __syncthreads();

        float acc[4][4][4];
        #pragma unroll
        for (int mi = 0; mi < 4; ++mi)
            #pragma unroll
            for (int ni = 0; ni < 4; ++ni)
                #pragma unroll
                for (int r = 0; r < 4; ++r) acc[mi][ni][r] = 0.f;

        mma_compute_full(sbase, sbase + TILE_BYTES + (jb & 1) * TILE_BYTES,
                         lane, wm, wn, acc);

        if (jb < 3) {
            // --- staged epilogue: frag -> smem (fp16) -> coalesced STG ---
            uint32_t stage_off = TILE_BYTES + (jb & 1) * TILE_BYTES;  // reuse consumed B buf
            __syncthreads();   // all warps done reading this B buffer
            #pragma unroll
            for (int mi = 0; mi < 4; ++mi) {
                #pragma unroll
                for (int ni = 0; ni < 4; ++ni) {
                    int col = wn * 32 + ni * 8 + (lane & 3) * 2;
                    float bb0 = g_bcat[widx * Jcols + jb * 128 + col];
                    float bb1 = g_bcat[widx * Jcols + jb * 128 + col + 1];
                    #pragma unroll
                    for (int h = 0; h < 2; ++h) {
                        int rloc = wm * 64 + mi * 16 + (lane >> 2) + h * 8;
                        float d0 = acc[mi][ni][h * 2 + 0] + bb0;
                        float d1 = acc[mi][ni][h * 2 + 1] + bb1;
                        *(uint32_t*)(smem + stage_off + rloc * (ASTR1 * 2) + col * 2) =
                            cvt16(d0, d1);
                    }
                }
            }
            __syncthreads();
            // coalesced store: CTA covers n in {n0, n0+1} x all 64 b
            int n0 = m0 >> 6;
            #pragma unroll
            for (int q = 0; q < 8; ++q) {
                int slot = q * 256 + tid;       // 2048 x 16B
                int b = slot >> 5;
                int rem = slot & 31;
                int nl = rem >> 4;              // 0..1
                int o8 = (rem & 15) * 8;        // 0..120
                uint4 v = *(uint4*)(smem + stage_off + (nl * 64 + b) * (ASTR1 * 2) + o8 * 2);
                *(uint4*)&g_supH[(((size_t)jb * Bb + b) * Nn + n0 + nl) * Oo + o8] = v;
            }
        } else {
            // highway gate: direct (1 of 4 jbs)
            #pragma unroll
            for (int mi = 0; mi < 4; ++mi) {
                #pragma unroll
                for (int ni = 0; ni < 4; ++ni) {
                    int col = wn * 32 + ni * 8 + (lane & 3) * 2;
                    float bb0 = g_bcat[widx * Jcols + jb * 128 + col];
                    float bb1 = g_bcat[widx * Jcols + jb * 128 + col + 1];
                    #pragma unroll
                    for (int h = 0; h < 2; ++h) {
                        int m = m0 + wm * 64 + mi * 16 + (lane >> 2) + h * 8;
                        float d0 = acc[mi][ni][h * 2 + 0] + bb0;
                        float d1 = acc[mi][ni][h * 2 + 1] + bb1;
                        float2 r;
                        r.x = 1.f / (1.f + expf(-d0));
                        r.y = 1.f / (1.f + expf(-d1));
                        *(float2*)&g_t[(size_t)m * Oo + col] = r;
                    }
                }
            }
        }

        // refill this jb's buffer for jb+2 only after all warps finished with it
        if (jb + 2 < 4) {
            __syncthreads();
            issueB(jb + 2);
        }
    }
}

// ---------------------------------------------------------------------------
// GEMM2 layer 1 (fp32 adj, register cvt, EMITS g_adjH): -> g_h (+g_hH)
// grid (4, 64). NCH=48, double-buffered. Wide (16B) A staging.
// ---------------------------------------------------------------------------
#define NCH2 48

__global__ __launch_bounds__(256, 2) void gemm2_mma(const float* __restrict__ adj,
                                                    const float* __restrict__ Xin) {
    extern __shared__ char smem[];
    uint32_t sbase = smem_u32(smem);

    int tid = threadIdx.x, lane = tid & 31, wid = tid >> 5;
    int wm = wid & 1, wn = wid >> 1;
    int m0 = blockIdx.x * 128, b = blockIdx.y;

    float acc[4][4][4];
    #pragma unroll
    for (int mi = 0; mi < 4; ++mi)
        #pragma unroll
        for (int ni = 0; ni < 4; ++ni)
            #pragma unroll
            for (int r = 0; r < 4; ++r) acc[mi][ni][r] = 0.f;

    int arow[2], ac8[2];
    #pragma unroll
    for (int q = 0; q < 2; ++q) { int s = q * 256 + tid; arow[q] = s >> 2; ac8[q] = s & 3; }
    float4 av[2][2];

    auto issueB = [&](int c) {
        uint32_t sb = sbase + (c & 1) * BUFSTRIDE;
        int e = c >> 4, n0 = (c & 15) * 32;
        size_t gb = (((size_t)e * Bb + b) * Nn + n0) * Oo;
        #pragma unroll
        for (int q = 0; q < 2; ++q) {
            int i = q * 256 + tid;
            int row = i >> 4, c8 = i & 15;
            cpa16(sb + BH_OFF + row * (BSTR * 2) + c8 * 16,
                  g_supH + gb + (size_t)row * Oo + c8 * 8);
        }
        cpa_commit();
    };
    auto loadA = [&](int c) {
        int e = c >> 4, n0 = (c & 15) * 32;
        const float* ab = adj + (((size_t)e * Bb + b) * Nn + m0) * Nn + n0;
        #pragma unroll
        for (int q = 0; q < 2; ++q) {
            const float* p = ab + (size_t)arow[q] * Nn + ac8[q] * 8;
            av[q][0] = *(const float4*)p;
            av[q][1] = *(const float4*)(p + 4);
        }
    };
    auto storeA = [&](int c) {
        uint32_t off = (c & 1) * BUFSTRIDE;
        int e = c >> 4, n0 = (c & 15) * 32;
        size_t ah_base = (((size_t)e * Bb + b) * Nn + m0) * Nn + n0;
        #pragma unroll
        for (int q = 0; q < 2; ++q) {
            uint4 hv;
            hv.x = cvt16(av[q][0].x, av[q][0].y);
            hv.y = cvt16(av[q][0].z, av[q][0].w);
            hv.z = cvt16(av[q][1].x, av[q][1].y);
            hv.w = cvt16(av[q][1].z, av[q][1].w);
            *(uint4*)(smem + off + arow[q] * (ASTR * 2) + ac8[q] * 16) = hv;
            *(uint4*)&g_adjH[ah_base + (size_t)arow[q] * Nn + ac8[q] * 8] = hv;
        }
    };

    issueB(0);
    loadA(0);
    storeA(0);
    for (int c = 0; c < NCH2; ++c) {
        cpa_wait0();
        __syncthreads();
        if (c + 1 < NCH2) { issueB(c + 1); loadA(c + 1); }
        mma_compute1(sbase + (c & 1) * BUFSTRIDE, lane, wm, wn, acc);
        if (c + 1 < NCH2) storeA(c + 1);
    }

    // epilogue: relu + highway gate -> g_h fp32 + g_hH fp16
    #pragma unroll
    for (int mi = 0; mi < 4; ++mi) {
        #pragma unroll
        for (int ni = 0; ni < 4; ++ni) {
            int col = wn * 32 + ni * 8 + (lane & 3) * 2;
            #pragma unroll
            for (int h = 0; h < 2; ++h) {
                int row = m0 + wm * 64 + mi * 16 + (lane >> 2) + h * 8;
                float d0 = acc[mi][ni][h * 2 + 0];
                float d1 = acc[mi][ni][h * 2 + 1];
                size_t base = ((size_t)row * Bb + b) * Oo + col;
                float2 tv = *(const float2*)&g_t[base];
                float2 xv = *(const float2*)&Xin[base];
                float2 r;
                r.x = fmaxf(d0, 0.f) * tv.x + xv.x * (1.f - tv.x);
                r.y = fmaxf(d1, 0.f) * tv.y + xv.y * (1.f - tv.y);
                *(float2*)&g_h[base] = r;
                *(uint32_t*)&g_hH[base] = cvt16(r.x, r.y);
            }
        }
    }
}

// ---------------------------------------------------------------------------
// GEMM2 layer 2 (pure fp16, 3-stage cp.async): -> d_out
// grid (4, 64). A from g_adjH, B from g_supH.
// ---------------------------------------------------------------------------
__global__ __launch_bounds__(256, 2) void gemm2_f16(float* __restrict__ Out) {
    extern __shared__ char smem[];
    uint32_t sbase = smem_u32(smem);

    int tid = threadIdx.x, lane = tid & 31, wid = tid >> 5;
    int wm = wid & 1, wn = wid >> 1;
    int m0 = blockIdx.x * 128, b = blockIdx.y;

    float acc[4][4][4];
    #pragma unroll
    for (int mi = 0; mi < 4; ++mi)
        #pragma unroll
        for (int ni = 0; ni < 4; ++ni)
            #pragma unroll
            for (int r = 0; r < 4; ++r) acc[mi][ni][r] = 0.f;

    auto issue = [&](int c) {
        uint32_t sb = sbase + (c % 3) * BUFSTRIDE;
        int e = c >> 4, n0 = (c & 15) * 32;
        size_t ab = (((size_t)e * Bb + b) * Nn + m0) * Nn + n0;
        #pragma unroll
        for (int q = 0; q < 2; ++q) {           // A: 128 rows x 32 halfs
            int i = q * 256 + tid;
            int row = i >> 2, c4 = i & 3;
            cpa16(sb + row * (ASTR * 2) + c4 * 16,
                  g_adjH + ab + (size_t)row * Nn + c4 * 8);
        }
        size_t gb = (((size_t)e * Bb + b) * Nn + n0) * Oo;
        #pragma unroll
        for (int q = 0; q < 2; ++q) {           // B: 32 rows x 128 cols
            int i = q * 256 + tid;
            int row = i >> 4, c8 = i & 15;
            cpa16(sb + BH_OFF + row * (BSTR * 2) + c8 * 16,
                  g_supH + gb + (size_t)row * Oo + c8 * 8);
        }
        cpa_commit();
    };

    issue(0);
    issue(1);
    for (int c = 0; c < NCH2; ++c) {
        if (c + 1 < NCH2) cpa_wait1(); else cpa_wait0();
        __syncthreads();
        if (c + 2 < NCH2) issue(c + 2);
        mma_compute1(sbase + (c % 3) * BUFSTRIDE, lane, wm, wn, acc);
    }

    // epilogue: relu + highway gate -> d_out
    #pragma unroll
    for (int mi = 0; mi < 4; ++mi) {
        #pragma unroll
        for (int ni = 0; ni < 4; ++ni) {
            int col = wn * 32 + ni * 8 + (lane & 3) * 2;
            #pragma unroll
            for (int h = 0; h < 2; ++h) {
                int row = m0 + wm * 64 + mi * 16 + (lane >> 2) + h * 8;
                float d0 = acc[mi][ni][h * 2 + 0];
                float d1 = acc[mi][ni][h * 2 + 1];
                size_t base = ((size_t)row * Bb + b) * Oo + col;
                float2 tv = *(const float2*)&g_t[base];
                float2 xv = *(const float2*)&g_h[base];
                float2 r;
                r.x = fmaxf(d0, 0.f) * tv.x + xv.x * (1.f - tv.x);
                r.y = fmaxf(d1, 0.f) * tv.y + xv.y * (1.f - tv.y);
                *(float2*)&Out[base] = r;
            }
        }
    }
}

extern "C" void kernel_launch(void* const* d_in, const int* in_sizes, int n_in,
                              void* d_out, int out_size) {
    const float* x   = (const float*)d_in[0];
    const float* adj = (const float*)d_in[1];
    const float* W1  = (const float*)d_in[2];
    const float* b1  = (const float*)d_in[3];
    const float* Wh1 = (const float*)d_in[4];
    const float* bh1 = (const float*)d_in[5];
    const float* W2  = (const float*)d_in[6];
    const float* b2  = (const float*)d_in[7];
    const float* Wh2 = (const float*)d_in[8];
    const float* bh2 = (const float*)d_in[9];
    float* out = (float*)d_out;

    static int attr_done = 0;
    if (!attr_done) {
        cudaFuncSetAttribute(gemm1_mma, cudaFuncAttributeMaxDynamicSharedMemorySize, SMEM_G1);
        cudaFuncSetAttribute(gemm2_mma, cudaFuncAttributeMaxDynamicSharedMemorySize, SMEM_2B);
        cudaFuncSetAttribute(gemm2_f16, cudaFuncAttributeMaxDynamicSharedMemorySize, SMEM_3B);
        attr_done = 1;
    }

    dim3 g2(Nn / 128, Bb);     // (4, 64)

    // Both weight preps up front
    prep_weights<<<Ff * Jcols / 2 / 256, 256>>>(W1, b1, Wh1, bh1, 0);
    prep_weights<<<Ff * Jcols / 2 / 256, 256>>>(W2, b2, Wh2, bh2, 1);
    x_split<<<Mrows * Ff / 4 / 256, 256>>>(x);

    // Layer 1
    gemm1_mma<<<Mrows / 128, 256, SMEM_G1>>>(0, 0);
    gemm2_mma<<<g2, 256, SMEM_2B>>>(adj, x);        // -> g_h, g_hH, g_adjH
    // Layer 2
    gemm1_mma<<<Mrows / 128, 256, SMEM_G1>>>(1, 1);
    gemm2_f16<<<g2, 256, SMEM_3B>>>(out);           // -> d_out
}

// round 16
// speedup vs baseline: 1.0883x; 1.0401x over previous
#include <cuda_runtime.h>
#include <cuda_fp16.h>
#include <math.h>
#include <stdint.h>

// Problem constants
#define Nn 512
#define Bb 64
#define Ff 128
#define Oo 128
#define Ee 3
#define Mrows (Nn*Bb)     // 32768
#define Jcols 512         // 3*O + O(highway)

// Scratch (static device globals)
__device__ float g_t[(size_t)Mrows*Oo];          // sigmoid gate [m, o] fp32
__device__ float g_bcat[2*Jcols];
__device__ __half g_WcatH[2*Ff*Jcols];           // weights fp16 (both layers)
__device__ __half g_xH[(size_t)Mrows*Ff];        // layer-1 X fp16
__device__ __half g_hH[(size_t)Mrows*Ff];        // layer-1 output fp16 (X + highway for L2)
__device__ __half g_supH[(size_t)Ee*Bb*Nn*Oo];   // support fp16 [e,b,n,o]
__device__ __half g_adjH[(size_t)Ee*Bb*Nn*Nn];   // adj fp16 (emitted by L1 gemm2)

// ---- fp16 convert ----
__device__ __forceinline__ uint32_t cvt16(float x, float y) {
    __half2 h = __floats2half2_rn(x, y);
    return *reinterpret_cast<uint32_t*>(&h);
}
__device__ __forceinline__ float2 h2f2(uint32_t v) {
    __half2 h = *reinterpret_cast<__half2*>(&v);
    return __half22float2(h);
}

__device__ __forceinline__ uint32_t smem_u32(const void* p) {
    uint32_t a;
    asm("{ .reg .u64 t; cvta.to.shared.u64 t, %1; cvt.u32.u64 %0, t; }" : "=r"(a) : "l"(p));
    return a;
}

// ---- cp.async ----
__device__ __forceinline__ void cpa16(uint32_t saddr, const void* g) {
    asm volatile("cp.async.cg.shared.global [%0], [%1], 16;" :: "r"(saddr), "l"(g));
}
__device__ __forceinline__ void cpa_commit() {
    asm volatile("cp.async.commit_group;" ::: "memory");
}
__device__ __forceinline__ void cpa_wait0() {
    asm volatile("cp.async.wait_group 0;" ::: "memory");
}
__device__ __forceinline__ void cpa_wait1() {
    asm volatile("cp.async.wait_group 1;" ::: "memory");
}

// ---- warp-level MMA primitives (fp16 in, fp32 accum) ----
__device__ __forceinline__ void ldsm4(uint32_t r[4], uint32_t addr) {
    asm volatile("ldmatrix.sync.aligned.m8n8.x4.shared.b16 {%0,%1,%2,%3}, [%4];"
                 : "=r"(r[0]), "=r"(r[1]), "=r"(r[2]), "=r"(r[3]) : "r"(addr));
}
__device__ __forceinline__ void ldsm4t(uint32_t r[4], uint32_t addr) {
    asm volatile("ldmatrix.sync.aligned.m8n8.x4.trans.shared.b16 {%0,%1,%2,%3}, [%4];"
                 : "=r"(r[0]), "=r"(r[1]), "=r"(r[2]), "=r"(r[3]) : "r"(addr));
}
__device__ __forceinline__ void mma16816(float c[4], const uint32_t a[4], const uint32_t b[2]) {
    asm volatile(
        "mma.sync.aligned.m16n8k16.row.col.f32.f16.f16.f32 "
        "{%0,%1,%2,%3}, {%4,%5,%6,%7}, {%8,%9}, {%0,%1,%2,%3};"
        : "+f"(c[0]), "+f"(c[1]), "+f"(c[2]), "+f"(c[3])
        : "r"(a[0]), "r"(a[1]), "r"(a[2]), "r"(a[3]), "r"(b[0]), "r"(b[1]));
}

// ---- shared tile geometry ----
// gemm2 (BK=32 chunks):
#define ASTR 40       // A smem row stride (half elems), 80 B
#define BSTR 136      // B smem row stride (half elems), 272 B
#define A_PLANE 10240 // 128*40*2
#define B_PLANE 8704  // 32*136*2
#define BH_OFF A_PLANE
#define BUFSTRIDE (A_PLANE + B_PLANE)   // 18944
#define SMEM_3B (3*BUFSTRIDE)           // 56832 (gemm2 L2, 3-stage; also >= 64*132*4 epi)
#define SMEM_2B (2*BUFSTRIDE)           // 37888 (gemm2 L1; also >= 128*136*2 epi)
// gemm1 (A resident, 2 B buffers, full K=128):
#define ASTR1 136
#define TILE_BYTES (128*ASTR1*2)        // 34816
#define SMEM_G1 (3*TILE_BYTES)          // 104448

// 1-pass compute on a BK=32 staged buffer. 2x4 warp grid, 64x32 warp tiles.
__device__ __forceinline__ void mma_compute1(uint32_t sb, int lane, int wm, int wn,
                                             float acc[4][4][4]) {
    #pragma unroll
    for (int ks = 0; ks < 2; ++ks) {
        int k0 = ks * 16;
        uint32_t abase = sb + ((wm * 64 + (lane & 15)) * ASTR + k0 + ((lane >> 4) << 3)) * 2;
        uint32_t bbase = sb + ((k0 + (lane & 15)) * BSTR + wn * 32 + ((lane >> 4) << 3)) * 2;

        uint32_t ah[4][4], bhf[4][2];
        #pragma unroll
        for (int mi = 0; mi < 4; ++mi)
            ldsm4(ah[mi], abase + mi * 16 * ASTR * 2);
        #pragma unroll
        for (int g = 0; g < 2; ++g) {
            uint32_t r[4];
            ldsm4t(r, bbase + BH_OFF + g * 32);
            bhf[g*2][0] = r[0]; bhf[g*2][1] = r[1];
            bhf[g*2+1][0] = r[2]; bhf[g*2+1][1] = r[3];
        }
        #pragma unroll
        for (int mi = 0; mi < 4; ++mi)
            #pragma unroll
            for (int ni = 0; ni < 4; ++ni)
                mma16816(acc[mi][ni], ah[mi], bhf[ni]);
    }
}

// full-K compute for gemm1
__device__ __forceinline__ void mma_compute_full(uint32_t abuf, uint32_t bbuf,
                                                 int lane, int wm, int wn,
                                                 float acc[4][4][4]) {
    #pragma unroll
    for (int ks = 0; ks < 8; ++ks) {
        int k0 = ks * 16;
        uint32_t abase = abuf + ((wm * 64 + (lane & 15)) * ASTR1 + k0 + ((lane >> 4) << 3)) * 2;
        uint32_t bbase = bbuf + ((k0 + (lane & 15)) * BSTR + wn * 32 + ((lane >> 4) << 3)) * 2;

        uint32_t ah[4][4], bhf[4][2];
        #pragma unroll
        for (int mi = 0; mi < 4; ++mi)
            ldsm4(ah[mi], abase + mi * 16 * ASTR1 * 2);
        #pragma unroll
        for (int g = 0; g < 2; ++g) {
            uint32_t r[4];
            ldsm4t(r, bbase + g * 32);
            bhf[g*2][0] = r[0]; bhf[g*2][1] = r[1];
            bhf[g*2+1][0] = r[2]; bhf[g*2+1][1] = r[3];
        }
        #pragma unroll
        for (int mi = 0; mi < 4; ++mi)
            #pragma unroll
            for (int ni = 0; ni < 4; ++ni)
                mma16816(acc[mi][ni], ah[mi], bhf[ni]);
    }
}

// ---------------------------------------------------------------------------
// prep_weights
// ---------------------------------------------------------------------------
__global__ void prep_weights(const float* __restrict__ W, const float* __restrict__ b,
                             const float* __restrict__ Wh, const float* __restrict__ bh,
                             int widx) {
    int idx = blockIdx.x * blockDim.x + threadIdx.x;
    if (idx < Ff * Jcols / 2) {
        int f = idx / (Jcols / 2), jp = idx % (Jcols / 2);
        int j = jp * 2;
        float v0, v1;
        if (j < 3 * Oo) {
            int e = j >> 7, o = j & 127;
            v0 = W[((size_t)e * Ff + f) * Oo + o];
            v1 = W[((size_t)e * Ff + f) * Oo + o + 1];
        } else {
            v0 = Wh[(size_t)f * Oo + (j - 3 * Oo)];
            v1 = Wh[(size_t)f * Oo + (j - 3 * Oo) + 1];
        }
        *(uint32_t*)&g_WcatH[widx * (Ff * Jcols) + f * Jcols + j] = cvt16(v0, v1);
    }
    if (idx < Jcols) {
        int j = idx;
        g_bcat[widx * Jcols + j] = (j < 3 * Oo) ? b[(j >> 7) * Oo + (j & 127)]
                                                : bh[j - 3 * Oo];
    }
}

// ---------------------------------------------------------------------------
// x_split
// ---------------------------------------------------------------------------
__global__ void x_split(const float* __restrict__ x) {
    int i = blockIdx.x * blockDim.x + threadIdx.x;
    float4 v = ((const float4*)x)[i];
    ((uint2*)g_xH)[i] = make_uint2(cvt16(v.x, v.y), cvt16(v.z, v.w));
}

// ---------------------------------------------------------------------------
// GEMM1 (fp16, A resident, jb-loop inside, staged support epilogue)
// ---------------------------------------------------------------------------
__global__ __launch_bounds__(256, 2) void gemm1_mma(int x_from_h, int widx) {
    extern __shared__ char smem[];
    const __half* __restrict__ XH = x_from_h ? g_hH : g_xH;
    const __half* __restrict__ WH = g_WcatH + (size_t)widx * Ff * Jcols;
    uint32_t sbase = smem_u32(smem);

    int tid = threadIdx.x, lane = tid & 31, wid = tid >> 5;
    int wm = wid & 1, wn = wid >> 1;
    int m0 = blockIdx.x * 128;

    auto issueB = [&](int jb) {
        uint32_t bb = sbase + TILE_BYTES + (jb & 1) * TILE_BYTES;
        #pragma unroll
        for (int q = 0; q < 8; ++q) {
            int i = q * 256 + tid;
            int row = i >> 4, c16 = i & 15;
            cpa16(bb + row * (BSTR * 2) + c16 * 16,
                  WH + (size_t)row * Jcols + jb * 128 + c16 * 8);
        }
        cpa_commit();
    };

    #pragma unroll
    for (int q = 0; q < 8; ++q) {
        int i = q * 256 + tid;
        int row = i >> 4, c16 = i & 15;
        cpa16(sbase + row * (ASTR1 * 2) + c16 * 16,
              XH + (size_t)(m0 + row) * Ff + c16 * 8);
    }
    issueB(0);
    issueB(1);

    #pragma unroll
    for (int jb = 0; jb < 4; ++jb) {
        if (jb < 3) cpa_wait1(); else cpa_wait0();
        __syncthreads();

        float acc[4][4][4];
        #pragma unroll
        for (int mi = 0; mi < 4; ++mi)
            #pragma unroll
            for (int ni = 0; ni < 4; ++ni)
                #pragma unroll
                for (int r = 0; r < 4; ++r) acc[mi][ni][r] = 0.f;

        mma_compute_full(sbase, sbase + TILE_BYTES + (jb & 1) * TILE_BYTES,
                         lane, wm, wn, acc);

        if (jb < 3) {
            uint32_t stage_off = TILE_BYTES + (jb & 1) * TILE_BYTES;
            __syncthreads();
            #pragma unroll
            for (int mi = 0; mi < 4; ++mi) {
                #pragma unroll
                for (int ni = 0; ni < 4; ++ni) {
                    int col = wn * 32 + ni * 8 + (lane & 3) * 2;
                    float bb0 = g_bcat[widx * Jcols + jb * 128 + col];
                    float bb1 = g_bcat[widx * Jcols + jb * 128 + col + 1];
                    #pragma unroll
                    for (int h = 0; h < 2; ++h) {
                        int rloc = wm * 64 + mi * 16 + (lane >> 2) + h * 8;
                        float d0 = acc[mi][ni][h * 2 + 0] + bb0;
                        float d1 = acc[mi][ni][h * 2 + 1] + bb1;
                        *(uint32_t*)(smem + stage_off + rloc * (ASTR1 * 2) + col * 2) =
                            cvt16(d0, d1);
                    }
                }
            }
            __syncthreads();
            int n0 = m0 >> 6;
            #pragma unroll
            for (int q = 0; q < 8; ++q) {
                int slot = q * 256 + tid;
                int b = slot >> 5;
                int rem = slot & 31;
                int nl = rem >> 4;
                int o8 = (rem & 15) * 8;
                uint4 v = *(uint4*)(smem + stage_off + (nl * 64 + b) * (ASTR1 * 2) + o8 * 2);
                *(uint4*)&g_supH[(((size_t)jb * Bb + b) * Nn + n0 + nl) * Oo + o8] = v;
            }
        } else {
            #pragma unroll
            for (int mi = 0; mi < 4; ++mi) {
                #pragma unroll
                for (int ni = 0; ni < 4; ++ni) {
                    int col = wn * 32 + ni * 8 + (lane & 3) * 2;
                    float bb0 = g_bcat[widx * Jcols + jb * 128 + col];
                    float bb1 = g_bcat[widx * Jcols + jb * 128 + col + 1];
                    #pragma unroll
                    for (int h = 0; h < 2; ++h) {
                        int m = m0 + wm * 64 + mi * 16 + (lane >> 2) + h * 8;
                        float d0 = acc[mi][ni][h * 2 + 0] + bb0;
                        float d1 = acc[mi][ni][h * 2 + 1] + bb1;
                        float2 r;
                        r.x = 1.f / (1.f + expf(-d0));
                        r.y = 1.f / (1.f + expf(-d1));
                        *(float2*)&g_t[(size_t)m * Oo + col] = r;
                    }
                }
            }
        }

        if (jb + 2 < 4) {
            __syncthreads();
            issueB(jb + 2);
        }
    }
}

// ---------------------------------------------------------------------------
// GEMM2 layer 1 (fp32 adj, register cvt, EMITS g_adjH): -> g_hH (staged)
// ---------------------------------------------------------------------------
#define NCH2 48

__global__ __launch_bounds__(256, 2) void gemm2_mma(const float* __restrict__ adj) {
    extern __shared__ char smem[];
    uint32_t sbase = smem_u32(smem);

    int tid = threadIdx.x, lane = tid & 31, wid = tid >> 5;
    int wm = wid & 1, wn = wid >> 1;
    int m0 = blockIdx.x * 128, b = blockIdx.y;

    float acc[4][4][4];
    #pragma unroll
    for (int mi = 0; mi < 4; ++mi)
        #pragma unroll
        for (int ni = 0; ni < 4; ++ni)
            #pragma unroll
            for (int r = 0; r < 4; ++r) acc[mi][ni][r] = 0.f;

    int arow[2], ac8[2];
    #pragma unroll
    for (int q = 0; q < 2; ++q) { int s = q * 256 + tid; arow[q] = s >> 2; ac8[q] = s & 3; }
    float4 av[2][2];

    auto issueB = [&](int c) {
        uint32_t sb = sbase + (c & 1) * BUFSTRIDE;
        int e = c >> 4, n0 = (c & 15) * 32;
        size_t gb = (((size_t)e * Bb + b) * Nn + n0) * Oo;
        #pragma unroll
        for (int q = 0; q < 2; ++q) {
            int i = q * 256 + tid;
            int row = i >> 4, c8 = i & 15;
            cpa16(sb + BH_OFF + row * (BSTR * 2) + c8 * 16,
                  g_supH + gb + (size_t)row * Oo + c8 * 8);
        }
        cpa_commit();
    };
    auto loadA = [&](int c) {
        int e = c >> 4, n0 = (c & 15) * 32;
        const float* ab = adj + (((size_t)e * Bb + b) * Nn + m0) * Nn + n0;
        #pragma unroll
        for (int q = 0; q < 2; ++q) {
            const float* p = ab + (size_t)arow[q] * Nn + ac8[q] * 8;
            av[q][0] = *(const float4*)p;
            av[q][1] = *(const float4*)(p + 4);
        }
    };
    auto storeA = [&](int c) {
        uint32_t off = (c & 1) * BUFSTRIDE;
        int e = c >> 4, n0 = (c & 15) * 32;
        size_t ah_base = (((size_t)e * Bb + b) * Nn + m0) * Nn + n0;
        #pragma unroll
        for (int q = 0; q < 2; ++q) {
            uint4 hv;
            hv.x = cvt16(av[q][0].x, av[q][0].y);
            hv.y = cvt16(av[q][0].z, av[q][0].w);
            hv.z = cvt16(av[q][1].x, av[q][1].y);
            hv.w = cvt16(av[q][1].z, av[q][1].w);
            *(uint4*)(smem + off + arow[q] * (ASTR * 2) + ac8[q] * 16) = hv;
            *(uint4*)&g_adjH[ah_base + (size_t)arow[q] * Nn + ac8[q] * 8] = hv;
        }
    };

    issueB(0);
    loadA(0);
    storeA(0);
    for (int c = 0; c < NCH2; ++c) {
        cpa_wait0();
        __syncthreads();
        if (c + 1 < NCH2) { issueB(c + 1); loadA(c + 1); }
        mma_compute1(sbase + (c & 1) * BUFSTRIDE, lane, wm, wn, acc);
        if (c + 1 < NCH2) storeA(c + 1);
    }

    // staged epilogue: gate in fragments, stage fp16 (stride 136), coalesced STG
    __syncthreads();
    #pragma unroll
    for (int mi = 0; mi < 4; ++mi) {
        #pragma unroll
        for (int ni = 0; ni < 4; ++ni) {
            int col = wn * 32 + ni * 8 + (lane & 3) * 2;
            #pragma unroll
            for (int h = 0; h < 2; ++h) {
                int rloc = wm * 64 + mi * 16 + (lane >> 2) + h * 8;
                size_t mb = ((size_t)(m0 + rloc) * Bb + b);
                float2 tv = *(const float2*)&g_t[mb * Oo + col];
                float2 xv = h2f2(*(const uint32_t*)&g_xH[mb * Ff + col]);
                float d0 = acc[mi][ni][h * 2 + 0];
                float d1 = acc[mi][ni][h * 2 + 1];
                float r0 = fmaxf(d0, 0.f) * tv.x + xv.x * (1.f - tv.x);
                float r1 = fmaxf(d1, 0.f) * tv.y + xv.y * (1.f - tv.y);
                *(uint32_t*)(smem + rloc * (BSTR * 2) + col * 2) = cvt16(r0, r1);
            }
        }
    }
    __syncthreads();
    #pragma unroll
    for (int q = 0; q < 8; ++q) {
        int slot = q * 256 + tid;           // 2048 uint4 slots
        int row = slot >> 4, o8 = (slot & 15) * 8;
        uint4 v = *(uint4*)(smem + row * (BSTR * 2) + o8 * 2);
        *(uint4*)&g_hH[((size_t)(m0 + row) * Bb + b) * Ff + o8] = v;
    }
}

// ---------------------------------------------------------------------------
// GEMM2 layer 2 (pure fp16, 3-stage cp.async): -> d_out (staged fp32 epilogue)
// ---------------------------------------------------------------------------
__global__ __launch_bounds__(256, 2) void gemm2_f16(float* __restrict__ Out) {
    extern __shared__ char smem[];
    uint32_t sbase = smem_u32(smem);

    int tid = threadIdx.x, lane = tid & 31, wid = tid >> 5;
    int wm = wid & 1, wn = wid >> 1;
    int m0 = blockIdx.x * 128, b = blockIdx.y;

    float acc[4][4][4];
    #pragma unroll
    for (int mi = 0; mi < 4; ++mi)
        #pragma unroll
        for (int ni = 0; ni < 4; ++ni)
            #pragma unroll
            for (int r = 0; r < 4; ++r) acc[mi][ni][r] = 0.f;

    auto issue = [&](int c) {
        uint32_t sb = sbase + (c % 3) * BUFSTRIDE;
        int e = c >> 4, n0 = (c & 15) * 32;
        size_t ab = (((size_t)e * Bb + b) * Nn + m0) * Nn + n0;
        #pragma unroll
        for (int q = 0; q < 2; ++q) {
            int i = q * 256 + tid;
            int row = i >> 2, c4 = i & 3;
            cpa16(sb + row * (ASTR * 2) + c4 * 16,
                  g_adjH + ab + (size_t)row * Nn + c4 * 8);
        }
        size_t gb = (((size_t)e * Bb + b) * Nn + n0) * Oo;
        #pragma unroll
        for (int q = 0; q < 2; ++q) {
            int i = q * 256 + tid;
            int row = i >> 4, c8 = i & 15;
            cpa16(sb + BH_OFF + row * (BSTR * 2) + c8 * 16,
                  g_supH + gb + (size_t)row * Oo + c8 * 8);
        }
        cpa_commit();
    };

    issue(0);
    issue(1);
    for (int c = 0; c < NCH2; ++c) {
        if (c + 1 < NCH2) cpa_wait1(); else cpa_wait0();
        __syncthreads();
        if (c + 2 < NCH2) issue(c + 2);
        mma_compute1(sbase + (c % 3) * BUFSTRIDE, lane, wm, wn, acc);
    }

    // staged fp32 epilogue in two 64-row passes (stride 132 floats = 528 B)
    __syncthreads();
    #pragma unroll
    for (int p = 0; p < 2; ++p) {
        if (wm == p) {
            #pragma unroll
            for (int mi = 0; mi < 4; ++mi) {
                #pragma unroll
                for (int ni = 0; ni < 4; ++ni) {
                    int col = wn * 32 + ni * 8 + (lane & 3) * 2;
                    #pragma unroll
                    for (int h = 0; h < 2; ++h) {
                        int rloc = mi * 16 + (lane >> 2) + h * 8;     // 0..63
                        int row = m0 + p * 64 + rloc;
                        size_t mb = ((size_t)row * Bb + b);
                        float2 tv = *(const float2*)&g_t[mb * Oo + col];
                        float2 xv = h2f2(*(const uint32_t*)&g_hH[mb * Ff + col]);
                        float d0 = acc[mi][ni][h * 2 + 0];
                        float d1 = acc[mi][ni][h * 2 + 1];
                        float2 r;
                        r.x = fmaxf(d0, 0.f) * tv.x + xv.x * (1.f - tv.x);
                        r.y = fmaxf(d1, 0.f) * tv.y + xv.y * (1.f - tv.y);
                        *(float2*)(smem + rloc * 528 + col * 4) = r;
                    }
                }
            }
        }
        __syncthreads();
        #pragma unroll
        for (int q = 0; q < 8; ++q) {
            int slot = q * 256 + tid;        // 2048 uint4 slots (64 rows x 32)
            int row = slot >> 5, o4 = (slot & 31) * 4;
            uint4 v = *(uint4*)(smem + row * 528 + o4 * 4);
            *(uint4*)&Out[((size_t)(m0 + p * 64 + row) * Bb + b) * Oo + o4] = v;
        }
        __syncthreads();
    }
}

extern "C" void kernel_launch(void* const* d_in, const int* in_sizes, int n_in,
                              void* d_out, int out_size) {
    const float* x   = (const float*)d_in[0];
    const float* adj = (const float*)d_in[1];
    const float* W1  = (const float*)d_in[2];
    const float* b1  = (const float*)d_in[3];
    const float* Wh1 = (const float*)d_in[4];
    const float* bh1 = (const float*)d_in[5];
    const float* W2  = (const float*)d_in[6];
    const float* b2  = (const float*)d_in[7];
    const float* Wh2 = (const float*)d_in[8];
    const float* bh2 = (const float*)d_in[9];
    float* out = (float*)d_out;

    static int attr_done = 0;
    if (!attr_done) {
        cudaFuncSetAttribute(gemm1_mma, cudaFuncAttributeMaxDynamicSharedMemorySize, SMEM_G1);
        cudaFuncSetAttribute(gemm2_mma, cudaFuncAttributeMaxDynamicSharedMemorySize, SMEM_2B);
        cudaFuncSetAttribute(gemm2_f16, cudaFuncAttributeMaxDynamicSharedMemorySize, SMEM_3B);
        attr_done = 1;
    }

    dim3 g2(Nn / 128, Bb);     // (4, 64)

    prep_weights<<<Ff * Jcols / 2 / 256, 256>>>(W1, b1, Wh1, bh1, 0);
    prep_weights<<<Ff * Jcols / 2 / 256, 256>>>(W2, b2, Wh2, bh2, 1);
    x_split<<<Mrows * Ff / 4 / 256, 256>>>(x);

    // Layer 1
    gemm1_mma<<<Mrows / 128, 256, SMEM_G1>>>(0, 0);
    gemm2_mma<<<g2, 256, SMEM_2B>>>(adj);           // -> g_hH, g_adjH
    // Layer 2
    gemm1_mma<<<Mrows / 128, 256, SMEM_G1>>>(1, 1);
    gemm2_f16<<<g2, 256, SMEM_3B>>>(out);           // -> d_out
}